// round 16
// baseline (speedup 1.0000x reference)
#include <cuda_runtime.h>
#include <math.h>
#include <stdint.h>

#define NB 32768

// ---------------- scratch (device globals: no allocation allowed) -------------
__device__ float    g_q  [NB * 64];     // [B,64]   q = center @ Wq^T
__device__ float    g_p  [NB * 512];    // [B,2,256] p[b,h] = q[b,h] @ Wk_h
__device__ uint32_t g_wn [NB * 256];    // [B,512] attention-weighted sum, PACKED bf16x2
__device__ float    g_ctx[NB * 256];    // context

// =============================================================================
// bf16 helpers (legacy mma.sync path — compute_103 baseline, no 'a' features)
// =============================================================================
__device__ __forceinline__ uint32_t packbf(float lo, float hi) {
    uint32_t r;
    asm("cvt.rn.bf16x2.f32 %0, %1, %2;" : "=r"(r) : "f"(hi), "f"(lo));
    return r;
}

__device__ __forceinline__ void mma_bf16(float* d, const uint32_t* a, const uint32_t* b) {
    asm volatile(
        "mma.sync.aligned.m16n8k16.row.col.f32.bf16.bf16.f32 "
        "{%0,%1,%2,%3}, {%4,%5,%6,%7}, {%8,%9}, {%0,%1,%2,%3};"
        : "+f"(d[0]), "+f"(d[1]), "+f"(d[2]), "+f"(d[3])
        : "r"(a[0]), "r"(a[1]), "r"(a[2]), "r"(a[3]), "r"(b[0]), "r"(b[1]));
}

// streaming (evict-first) float4 load — for the once-read neigh stream
__device__ __forceinline__ float4 ldcs4(const float* p) {
    float4 v;
    asm("ld.global.cs.v4.f32 {%0,%1,%2,%3}, [%4];"
        : "=f"(v.x), "=f"(v.y), "=f"(v.z), "=f"(v.w) : "l"(p));
    return v;
}

#define AS32_STR 20   // u32 stride per row: (20r+c) mod 32 over frag set = permutation

// =============================================================================
// BN=64 GEMM (proven round-11 version) — used for q only.
// =============================================================================
#define AS32_CNT (128 * AS32_STR)    // 2560 u32 per A buffer
#define WS32_CNT (64 * AS32_STR)     // 1280 u32 per W buffer
#define GEMM_SMEM_BYTES ((2 * AS32_CNT + 2 * WS32_CNT) * 4)    // 30720

__global__ __launch_bounds__(256) void gemm_q(
    const float* __restrict__ A, const float* __restrict__ W,
    float* __restrict__ C, int lda, int ldw, int ldc)
{
    extern __shared__ uint32_t ds[];
    uint32_t* Asb[2] = {ds, ds + AS32_CNT};
    uint32_t* Wsb[2] = {ds + 2 * AS32_CNT, ds + 2 * AS32_CNT + WS32_CNT};

    const int tid  = threadIdx.x;
    const int wid  = tid >> 5;
    const int lane = tid & 31;
    const int m0   = blockIdx.x * 128;
    const int wm   = (wid & 3) * 32;
    const int wn   = (wid >> 2) * 32;

    float4 ra[4], rw[2];
#pragma unroll
    for (int i = 0; i < 4; i++) {
        const int idx = tid + 256 * i, r = idx >> 3, kq = idx & 7;
        ra[i] = *(const float4*)(A + (size_t)(m0 + r) * lda + kq * 4);
    }
#pragma unroll
    for (int i = 0; i < 2; i++) {
        const int idx = tid + 256 * i, r = idx >> 3, kq = idx & 7;
        rw[i] = *(const float4*)(W + (size_t)r * ldw + kq * 4);
    }

    float acc[2][4][4];
#pragma unroll
    for (int i = 0; i < 2; i++)
#pragma unroll
        for (int j = 0; j < 4; j++)
#pragma unroll
            for (int v = 0; v < 4; v++) acc[i][j][v] = 0.f;

    {
        uint32_t* As = Asb[0];
        uint32_t* Ws = Wsb[0];
#pragma unroll
        for (int i = 0; i < 4; i++) {
            const int idx = tid + 256 * i, r = idx >> 3, kq = idx & 7;
            uint2 u = {packbf(ra[i].x, ra[i].y), packbf(ra[i].z, ra[i].w)};
            *(uint2*)&As[r * AS32_STR + kq * 2] = u;
        }
#pragma unroll
        for (int i = 0; i < 2; i++) {
            const int idx = tid + 256 * i, r = idx >> 3, kq = idx & 7;
            uint2 u = {packbf(rw[i].x, rw[i].y), packbf(rw[i].z, rw[i].w)};
            *(uint2*)&Ws[r * AS32_STR + kq * 2] = u;
        }
    }
    __syncthreads();

#pragma unroll 1
    for (int it = 0; it < 8; it++) {
        const int cur = it & 1;
        if (it < 7) {
            const int kb = (it + 1) * 32;
#pragma unroll
            for (int i = 0; i < 4; i++) {
                const int idx = tid + 256 * i, r = idx >> 3, kq = idx & 7;
                ra[i] = *(const float4*)(A + (size_t)(m0 + r) * lda + kb + kq * 4);
            }
#pragma unroll
            for (int i = 0; i < 2; i++) {
                const int idx = tid + 256 * i, r = idx >> 3, kq = idx & 7;
                rw[i] = *(const float4*)(W + (size_t)r * ldw + kb + kq * 4);
            }
        }
        {
            const uint32_t* As = Asb[cur];
            const uint32_t* Ws = Wsb[cur];
            const int c = lane & 3, r = lane >> 2;
#pragma unroll
            for (int ks = 0; ks < 2; ks++) {
                const int kp = ks * 8;
                uint32_t afr[2][4], bfr[4][2];
#pragma unroll
                for (int i = 0; i < 2; i++) {
                    const int r0 = wm + i * 16 + r;
                    afr[i][0] = As[r0 * AS32_STR + kp + c];
                    afr[i][1] = As[(r0 + 8) * AS32_STR + kp + c];
                    afr[i][2] = As[r0 * AS32_STR + kp + c + 4];
                    afr[i][3] = As[(r0 + 8) * AS32_STR + kp + c + 4];
                }
#pragma unroll
                for (int j = 0; j < 4; j++) {
                    const int c0 = wn + j * 8 + r;
                    bfr[j][0] = Ws[c0 * AS32_STR + kp + c];
                    bfr[j][1] = Ws[c0 * AS32_STR + kp + c + 4];
                }
#pragma unroll
                for (int i = 0; i < 2; i++)
#pragma unroll
                    for (int j = 0; j < 4; j++)
                        mma_bf16(acc[i][j], afr[i], bfr[j]);
            }
        }
        if (it < 7) {
            uint32_t* As = Asb[1 - cur];
            uint32_t* Ws = Wsb[1 - cur];
#pragma unroll
            for (int i = 0; i < 4; i++) {
                const int idx = tid + 256 * i, r = idx >> 3, kq = idx & 7;
                uint2 u = {packbf(ra[i].x, ra[i].y), packbf(ra[i].z, ra[i].w)};
                *(uint2*)&As[r * AS32_STR + kq * 2] = u;
            }
#pragma unroll
            for (int i = 0; i < 2; i++) {
                const int idx = tid + 256 * i, r = idx >> 3, kq = idx & 7;
                uint2 u = {packbf(rw[i].x, rw[i].y), packbf(rw[i].z, rw[i].w)};
                *(uint2*)&Ws[r * AS32_STR + kq * 2] = u;
            }
        }
        __syncthreads();
    }

    const int r = lane >> 2, c2 = (lane & 3) * 2;
#pragma unroll
    for (int i = 0; i < 2; i++)
#pragma unroll
        for (int j = 0; j < 4; j++) {
            const int row0 = m0 + wm + i * 16 + r;
            const int col  = wn + j * 8 + c2;
#pragma unroll
            for (int half = 0; half < 2; half++)
                *(float2*)(C + (size_t)(row0 + half * 8) * ldc + col) =
                    make_float2(acc[i][j][2 * half], acc[i][j][2 * half + 1]);
        }
}

// =============================================================================
// BN=128 GEMM body, fp32 A (gate): CTA 128x128, 8 warps 2(m)x4(n).
// NCHUNK chunks of K=32; chunk c reads A_lo if c<8 else A_hi (virtual concat).
// EPI=1: out = g*A_lo + (1-g)*A_hi, g = sigmoid(acc + bias).
// =============================================================================
#define W128_CNT (128 * AS32_STR)
#define GEMM128_SMEM_BYTES ((2 * AS32_CNT + 2 * W128_CNT) * 4)   // 40960

template <int NCHUNK, int EPI>
__device__ __forceinline__ void gemm_body128(
    const float* __restrict__ A_lo, const float* __restrict__ A_hi,
    const float* __restrict__ W,
    float* __restrict__ C, int lda, int ldw, int ldc, int m0, int n0,
    const float* __restrict__ bias, float* __restrict__ outp, uint32_t* ds)
{
    uint32_t* Asb[2] = {ds, ds + AS32_CNT};
    uint32_t* Wsb[2] = {ds + 2 * AS32_CNT, ds + 2 * AS32_CNT + W128_CNT};

    const int tid  = threadIdx.x;
    const int wid  = tid >> 5;
    const int lane = tid & 31;
    const int wm   = (wid & 1) * 64;
    const int wn   = (wid >> 1) * 32;

    float4 ra[4], rw[4];
#pragma unroll
    for (int i = 0; i < 4; i++) {
        const int idx = tid + 256 * i, r = idx >> 3, kq = idx & 7;
        ra[i] = *(const float4*)(A_lo + (size_t)(m0 + r) * lda + kq * 4);
        rw[i] = *(const float4*)(W + (size_t)(n0 + r) * ldw + kq * 4);
    }

    float acc[4][4][4];
#pragma unroll
    for (int i = 0; i < 4; i++)
#pragma unroll
        for (int j = 0; j < 4; j++)
#pragma unroll
            for (int v = 0; v < 4; v++) acc[i][j][v] = 0.f;

    {
        uint32_t* As = Asb[0];
        uint32_t* Ws = Wsb[0];
#pragma unroll
        for (int i = 0; i < 4; i++) {
            const int idx = tid + 256 * i, r = idx >> 3, kq = idx & 7;
            uint2 ua = {packbf(ra[i].x, ra[i].y), packbf(ra[i].z, ra[i].w)};
            uint2 uw = {packbf(rw[i].x, rw[i].y), packbf(rw[i].z, rw[i].w)};
            *(uint2*)&As[r * AS32_STR + kq * 2] = ua;
            *(uint2*)&Ws[r * AS32_STR + kq * 2] = uw;
        }
    }
    __syncthreads();

#pragma unroll 1
    for (int it = 0; it < NCHUNK; it++) {
        const int cur = it & 1;
        if (it < NCHUNK - 1) {
            const int nc = it + 1;
            const float* Abase = (NCHUNK == 8 || nc < 8) ? A_lo : A_hi;
            const int ka = (NCHUNK == 8 || nc < 8) ? nc * 32 : (nc - 8) * 32;
#pragma unroll
            for (int i = 0; i < 4; i++) {
                const int idx = tid + 256 * i, r = idx >> 3, kq = idx & 7;
                ra[i] = *(const float4*)(Abase + (size_t)(m0 + r) * lda + ka + kq * 4);
                rw[i] = *(const float4*)(W + (size_t)(n0 + r) * ldw + nc * 32 + kq * 4);
            }
        }
        {
            const uint32_t* As = Asb[cur];
            const uint32_t* Ws = Wsb[cur];
            const int c = lane & 3, r = lane >> 2;
#pragma unroll
            for (int ks = 0; ks < 2; ks++) {
                const int kp = ks * 8;
                uint32_t afr[4][4], bfr[4][2];
#pragma unroll
                for (int i = 0; i < 4; i++) {
                    const int r0 = wm + i * 16 + r;
                    afr[i][0] = As[r0 * AS32_STR + kp + c];
                    afr[i][1] = As[(r0 + 8) * AS32_STR + kp + c];
                    afr[i][2] = As[r0 * AS32_STR + kp + c + 4];
                    afr[i][3] = As[(r0 + 8) * AS32_STR + kp + c + 4];
                }
#pragma unroll
                for (int j = 0; j < 4; j++) {
                    const int c0 = wn + j * 8 + r;
                    bfr[j][0] = Ws[c0 * AS32_STR + kp + c];
                    bfr[j][1] = Ws[c0 * AS32_STR + kp + c + 4];
                }
#pragma unroll
                for (int i = 0; i < 4; i++)
#pragma unroll
                    for (int j = 0; j < 4; j++)
                        mma_bf16(acc[i][j], afr[i], bfr[j]);
            }
        }
        if (it < NCHUNK - 1) {
            uint32_t* As = Asb[1 - cur];
            uint32_t* Ws = Wsb[1 - cur];
#pragma unroll
            for (int i = 0; i < 4; i++) {
                const int idx = tid + 256 * i, r = idx >> 3, kq = idx & 7;
                uint2 ua = {packbf(ra[i].x, ra[i].y), packbf(ra[i].z, ra[i].w)};
                uint2 uw = {packbf(rw[i].x, rw[i].y), packbf(rw[i].z, rw[i].w)};
                *(uint2*)&As[r * AS32_STR + kq * 2] = ua;
                *(uint2*)&Ws[r * AS32_STR + kq * 2] = uw;
            }
        }
        __syncthreads();
    }

    const int r = lane >> 2, c2 = (lane & 3) * 2;
#pragma unroll
    for (int i = 0; i < 4; i++) {
#pragma unroll
        for (int j = 0; j < 4; j++) {
            const int row0 = m0 + wm + i * 16 + r;
            const int col  = n0 + wn + j * 8 + c2;
#pragma unroll
            for (int half = 0; half < 2; half++) {
                const int row = row0 + half * 8;
                const float d0 = acc[i][j][2 * half + 0];
                const float d1 = acc[i][j][2 * half + 1];
                if (EPI == 0) {
                    *(float2*)(C + (size_t)row * ldc + col) = make_float2(d0, d1);
                } else {
                    const float2 bv = *(const float2*)(bias + col);
                    const float2 cv = *(const float2*)(A_lo + (size_t)row * lda + col);
                    const float2 xv = *(const float2*)(A_hi + (size_t)row * lda + col);
                    const float gg0 = 1.f / (1.f + __expf(-(d0 + bv.x)));
                    const float gg1 = 1.f / (1.f + __expf(-(d1 + bv.y)));
                    float2 o;
                    o.x = gg0 * cv.x + (1.f - gg0) * xv.x;
                    o.y = gg1 * cv.y + (1.f - gg1) * xv.y;
                    *(float2*)(outp + (size_t)row * 256 + col) = o;
                }
            }
        }
    }
}

// gate: K=512 virtual concat(center, ctx); N=256 in 2 y-blocks.
__global__ __launch_bounds__(256, 2) void gemm_gate128(
    const float* __restrict__ center, const float* __restrict__ ctx,
    const float* __restrict__ Wg, const float* __restrict__ bias,
    float* __restrict__ outp)
{
    extern __shared__ uint32_t dsu[];
    gemm_body128<16, 1>(center, ctx, Wg, nullptr, 256, 512, 0,
                        blockIdx.x * 128, blockIdx.y * 128, bias, outp, dsu);
}

// =============================================================================
// ctx GEMM, bf16 A (wn is pre-packed bf16x2): CTA 128x128, head = blockIdx.y.
// =============================================================================
__global__ __launch_bounds__(256, 2) void gemm_ctx_bf(
    const uint32_t* __restrict__ wnp, const float* __restrict__ Wv,
    float* __restrict__ ctx_)
{
    extern __shared__ uint32_t dsu[];
    uint32_t* Asb[2] = {dsu, dsu + AS32_CNT};
    uint32_t* Wsb[2] = {dsu + 2 * AS32_CNT, dsu + 2 * AS32_CNT + W128_CNT};

    const int h = blockIdx.y;
    const uint32_t* A = wnp + h * 128;         // row stride 256 u32
    const float* W = Wv + h * 128 * 256;       // [128, 256] for this head
    float* C = ctx_ + h * 128;

    const int tid  = threadIdx.x;
    const int wid  = tid >> 5;
    const int lane = tid & 31;
    const int m0   = blockIdx.x * 128;
    const int wm   = (wid & 1) * 64;
    const int wn   = (wid >> 1) * 32;

    uint2 ra[4];
    float4 rw[4];
#pragma unroll
    for (int i = 0; i < 4; i++) {
        const int idx = tid + 256 * i, r = idx >> 3, kq = idx & 7;
        ra[i] = *(const uint2*)(A + (size_t)(m0 + r) * 256 + kq * 2);
        rw[i] = *(const float4*)(W + (size_t)r * 256 + kq * 4);
    }

    float acc[4][4][4];
#pragma unroll
    for (int i = 0; i < 4; i++)
#pragma unroll
        for (int j = 0; j < 4; j++)
#pragma unroll
            for (int v = 0; v < 4; v++) acc[i][j][v] = 0.f;

    {
        uint32_t* As = Asb[0];
        uint32_t* Ws = Wsb[0];
#pragma unroll
        for (int i = 0; i < 4; i++) {
            const int idx = tid + 256 * i, r = idx >> 3, kq = idx & 7;
            *(uint2*)&As[r * AS32_STR + kq * 2] = ra[i];
            uint2 uw = {packbf(rw[i].x, rw[i].y), packbf(rw[i].z, rw[i].w)};
            *(uint2*)&Ws[r * AS32_STR + kq * 2] = uw;
        }
    }
    __syncthreads();

#pragma unroll 1
    for (int it = 0; it < 8; it++) {
        const int cur = it & 1;
        if (it < 7) {
            const int nc = it + 1;
#pragma unroll
            for (int i = 0; i < 4; i++) {
                const int idx = tid + 256 * i, r = idx >> 3, kq = idx & 7;
                ra[i] = *(const uint2*)(A + (size_t)(m0 + r) * 256 + nc * 16 + kq * 2);
                rw[i] = *(const float4*)(W + (size_t)r * 256 + nc * 32 + kq * 4);
            }
        }
        {
            const uint32_t* As = Asb[cur];
            const uint32_t* Ws = Wsb[cur];
            const int c = lane & 3, r = lane >> 2;
#pragma unroll
            for (int ks = 0; ks < 2; ks++) {
                const int kp = ks * 8;
                uint32_t afr[4][4], bfr[4][2];
#pragma unroll
                for (int i = 0; i < 4; i++) {
                    const int r0 = wm + i * 16 + r;
                    afr[i][0] = As[r0 * AS32_STR + kp + c];
                    afr[i][1] = As[(r0 + 8) * AS32_STR + kp + c];
                    afr[i][2] = As[r0 * AS32_STR + kp + c + 4];
                    afr[i][3] = As[(r0 + 8) * AS32_STR + kp + c + 4];
                }
#pragma unroll
                for (int j = 0; j < 4; j++) {
                    const int c0 = wn + j * 8 + r;
                    bfr[j][0] = Ws[c0 * AS32_STR + kp + c];
                    bfr[j][1] = Ws[c0 * AS32_STR + kp + c + 4];
                }
#pragma unroll
                for (int i = 0; i < 4; i++)
#pragma unroll
                    for (int j = 0; j < 4; j++)
                        mma_bf16(acc[i][j], afr[i], bfr[j]);
            }
        }
        if (it < 7) {
            uint32_t* As = Asb[1 - cur];
            uint32_t* Ws = Wsb[1 - cur];
#pragma unroll
            for (int i = 0; i < 4; i++) {
                const int idx = tid + 256 * i, r = idx >> 3, kq = idx & 7;
                *(uint2*)&As[r * AS32_STR + kq * 2] = ra[i];
                uint2 uw = {packbf(rw[i].x, rw[i].y), packbf(rw[i].z, rw[i].w)};
                *(uint2*)&Ws[r * AS32_STR + kq * 2] = uw;
            }
        }
        __syncthreads();
    }

    const int r = lane >> 2, c2 = (lane & 3) * 2;
#pragma unroll
    for (int i = 0; i < 4; i++)
#pragma unroll
        for (int j = 0; j < 4; j++) {
            const int row0 = m0 + wm + i * 16 + r;
            const int col  = wn + j * 8 + c2;
#pragma unroll
            for (int half = 0; half < 2; half++)
                *(float2*)(C + (size_t)(row0 + half * 8) * 256 + col) =
                    make_float2(acc[i][j][2 * half], acc[i][j][2 * half + 1]);
        }
}

// =============================================================================
// p kernel:  p[b,h,d] = sum_{a<32} q[b, h*32+a] * Wk[h*32+a, d]   (fp32)
// =============================================================================
__global__ __launch_bounds__(256) void p_kernel(const float* __restrict__ Wk)
{
    __shared__ float qs[16 * 64];
    const int t = threadIdx.x;              // t == d
    float wk[64];
#pragma unroll
    for (int r = 0; r < 64; r++) wk[r] = Wk[r * 256 + t];

    const int b0 = blockIdx.x * 16;
    const float4* qsrc = (const float4*)(g_q + (size_t)b0 * 64);
    ((float4*)qs)[t] = qsrc[t];
    __syncthreads();

#pragma unroll 1
    for (int bb = 0; bb < 16; bb++) {
        float p0 = 0.f, p1 = 0.f;
#pragma unroll
        for (int a4 = 0; a4 < 8; a4++) {
            const float4 q0 = *(const float4*)&qs[bb * 64 + a4 * 4];
            const float4 q1 = *(const float4*)&qs[bb * 64 + 32 + a4 * 4];
            p0 = fmaf(q0.x, wk[a4 * 4 + 0], p0);
            p0 = fmaf(q0.y, wk[a4 * 4 + 1], p0);
            p0 = fmaf(q0.z, wk[a4 * 4 + 2], p0);
            p0 = fmaf(q0.w, wk[a4 * 4 + 3], p0);
            p1 = fmaf(q1.x, wk[32 + a4 * 4 + 0], p1);
            p1 = fmaf(q1.y, wk[32 + a4 * 4 + 1], p1);
            p1 = fmaf(q1.z, wk[32 + a4 * 4 + 2], p1);
            p1 = fmaf(q1.w, wk[32 + a4 * 4 + 3], p1);
        }
        const size_t o = (size_t)(b0 + bb) * 512;
        g_p[o + t]       = p0;
        g_p[o + 256 + t] = p1;
    }
}

// =============================================================================
// Register-resident attention (proven mainloop + packed-bf16 wn epilogue).
// NEW: neigh loads use ld.global.cs (evict-first) — the 2.15GB once-read
// stream no longer sweeps L2, preserving it for p/wn/weights reuse.
// =============================================================================
__global__ __launch_bounds__(256) void attn_reg(
    const float* __restrict__ neigh, const float* __restrict__ wts)
{
    __shared__ float sAcc[8][512];        // 16 KB cross-warp reduction
    __shared__ float sScore[2][64];
    __shared__ float sAttn[2][64];
    __shared__ float sWt[64];

    const int b    = blockIdx.x;
    const int t    = threadIdx.x;
    const int w    = t >> 5;
    const int lane = t & 31;

    if (t < 64) sWt[t] = wts[(size_t)b * 64 + t] * 0.17677669529663687f; // /sqrt(32)

    const float4* pp = (const float4*)(g_p + (size_t)b * 512);
    const float4 p0a = pp[lane];
    const float4 p0b = pp[32 + lane];
    const float4 p1a = pp[64 + lane];
    const float4 p1b = pp[96 + lane];

    const float* nbp = neigh + (size_t)b * 64 * 256;

    float4 va[8], vb[8];
#pragma unroll
    for (int it = 0; it < 8; it++) {            // front-batched: 16 LDG.128.CS
        const int k = it * 8 + w;
        va[it] = ldcs4(nbp + k * 256 + 4 * lane);
        vb[it] = ldcs4(nbp + k * 256 + 128 + 4 * lane);
    }

#pragma unroll
    for (int it = 0; it < 8; it++) {
        float s0 = va[it].x * p0a.x + va[it].y * p0a.y + va[it].z * p0a.z + va[it].w * p0a.w
                 + vb[it].x * p0b.x + vb[it].y * p0b.y + vb[it].z * p0b.z + vb[it].w * p0b.w;
        float s1 = va[it].x * p1a.x + va[it].y * p1a.y + va[it].z * p1a.z + va[it].w * p1a.w
                 + vb[it].x * p1b.x + vb[it].y * p1b.y + vb[it].z * p1b.z + vb[it].w * p1b.w;
#pragma unroll
        for (int o = 16; o; o >>= 1) {
            s0 += __shfl_xor_sync(0xffffffffu, s0, o);
            s1 += __shfl_xor_sync(0xffffffffu, s1, o);
        }
        if (lane == 0) {
            sScore[0][it * 8 + w] = s0;
            sScore[1][it * 8 + w] = s1;
        }
    }
    __syncthreads();

    if (t < 64) {                    // warps 0,1: one head each
        const int h = t >> 5, l = t & 31;
        const float sa = sScore[h][l]      * sWt[l];
        const float sb = sScore[h][32 + l] * sWt[32 + l];
        float mx = fmaxf(sa, sb);
#pragma unroll
        for (int o = 16; o; o >>= 1) mx = fmaxf(mx, __shfl_xor_sync(0xffffffffu, mx, o));
        const float ea = __expf(sa - mx), eb = __expf(sb - mx);
        float sum = ea + eb;
#pragma unroll
        for (int o = 16; o; o >>= 1) sum += __shfl_xor_sync(0xffffffffu, sum, o);
        const float inv = 1.f / sum;
        sAttn[h][l]      = ea * inv;
        sAttn[h][32 + l] = eb * inv;
    }
    __syncthreads();

    float4 a0a = {0,0,0,0}, a0b = {0,0,0,0}, a1a = {0,0,0,0}, a1b = {0,0,0,0};
#pragma unroll
    for (int it = 0; it < 8; it++) {
        const float w0 = sAttn[0][it * 8 + w];   // warp-uniform broadcast
        const float w1 = sAttn[1][it * 8 + w];
        a0a.x = fmaf(w0, va[it].x, a0a.x);  a0a.y = fmaf(w0, va[it].y, a0a.y);
        a0a.z = fmaf(w0, va[it].z, a0a.z);  a0a.w = fmaf(w0, va[it].w, a0a.w);
        a0b.x = fmaf(w0, vb[it].x, a0b.x);  a0b.y = fmaf(w0, vb[it].y, a0b.y);
        a0b.z = fmaf(w0, vb[it].z, a0b.z);  a0b.w = fmaf(w0, vb[it].w, a0b.w);
        a1a.x = fmaf(w1, va[it].x, a1a.x);  a1a.y = fmaf(w1, va[it].y, a1a.y);
        a1a.z = fmaf(w1, va[it].z, a1a.z);  a1a.w = fmaf(w1, va[it].w, a1a.w);
        a1b.x = fmaf(w1, vb[it].x, a1b.x);  a1b.y = fmaf(w1, vb[it].y, a1b.y);
        a1b.z = fmaf(w1, vb[it].z, a1b.z);  a1b.w = fmaf(w1, vb[it].w, a1b.w);
    }

    float4* row = (float4*)&sAcc[w][0];
    row[lane]      = a0a;
    row[32 + lane] = a0b;
    row[64 + lane] = a1a;
    row[96 + lane] = a1b;
    __syncthreads();

    // thread t -> one u32 of packed wn: head h = t>>7, bf16 cols 2*(t&127), +1
    const int hh = t >> 7;
    const int c0 = hh * 256 + (t & 127) * 2;
    float s_e = 0.f, s_o = 0.f;
#pragma unroll
    for (int ww = 0; ww < 8; ww++) {
        const float2 v = *(const float2*)&sAcc[ww][c0];
        s_e += v.x;
        s_o += v.y;
    }
    g_wn[(size_t)b * 256 + t] = packbf(s_e, s_o);
}

// =============================================================================
extern "C" void kernel_launch(void* const* d_in, const int* in_sizes, int n_in,
                              void* d_out, int out_size)
{
    const float* center = (const float*)d_in[0];
    const float* neigh  = (const float*)d_in[1];
    const float* wts    = (const float*)d_in[2];
    const float* Wq     = (const float*)d_in[3];
    const float* Wk     = (const float*)d_in[4];
    const float* Wv     = (const float*)d_in[5];
    const float* Wg     = (const float*)d_in[6];
    const float* bg     = (const float*)d_in[7];
    float* out = (float*)d_out;

    float *q_, *ctx_;
    uint32_t* wn_;
    cudaGetSymbolAddress((void**)&q_,   g_q);
    cudaGetSymbolAddress((void**)&wn_,  g_wn);
    cudaGetSymbolAddress((void**)&ctx_, g_ctx);

    cudaFuncSetAttribute(gemm_q,
                         cudaFuncAttributeMaxDynamicSharedMemorySize, GEMM_SMEM_BYTES);
    cudaFuncSetAttribute(gemm_ctx_bf,
                         cudaFuncAttributeMaxDynamicSharedMemorySize, GEMM128_SMEM_BYTES);
    cudaFuncSetAttribute(gemm_gate128,
                         cudaFuncAttributeMaxDynamicSharedMemorySize, GEMM128_SMEM_BYTES);

    const dim3 blk(256);

    // q = center @ Wq^T                       [B,64]
    gemm_q<<<dim3(256), blk, GEMM_SMEM_BYTES>>>(center, Wq, q_, 256, 256, 64);
    // p[b,h] = q[b,h] @ Wk_h                  [B,2,256]
    p_kernel<<<2048, blk>>>(Wk);
    // attention -> wn (packed bf16x2)         [B,512]
    attn_reg<<<NB, blk>>>(neigh, wts);
    // context_h = wn_h @ Wv_h^T               [B,256] (head = blockIdx.y)
    gemm_ctx_bf<<<dim3(256, 2), blk, GEMM128_SMEM_BYTES>>>(wn_, Wv, ctx_);
    // gate = sigmoid(concat(center,ctx) @ Wg^T + bg); out = gate*center+(1-gate)*ctx
    gemm_gate128<<<dim3(256, 2), blk, GEMM128_SMEM_BYTES>>>(center, ctx_, Wg, bg, out);
}

// round 17
// speedup vs baseline: 1.0233x; 1.0233x over previous
#include <cuda_runtime.h>
#include <math.h>
#include <stdint.h>

#define NB 32768

// ---------------- scratch (device globals: no allocation allowed) -------------
__device__ float    g_q  [NB * 64];     // [B,64]   q = center @ Wq^T
__device__ float    g_p  [NB * 512];    // [B,2,256] p[b,h] = q[b,h] @ Wk_h
__device__ uint32_t g_wn [NB * 256];    // [B,512] attention-weighted sum, PACKED bf16x2
__device__ float    g_ctx[NB * 256];    // context

// =============================================================================
// bf16 helpers (legacy mma.sync path — compute_103 baseline, no 'a' features)
// =============================================================================
__device__ __forceinline__ uint32_t packbf(float lo, float hi) {
    uint32_t r;
    asm("cvt.rn.bf16x2.f32 %0, %1, %2;" : "=r"(r) : "f"(hi), "f"(lo));
    return r;
}

__device__ __forceinline__ void mma_bf16(float* d, const uint32_t* a, const uint32_t* b) {
    asm volatile(
        "mma.sync.aligned.m16n8k16.row.col.f32.bf16.bf16.f32 "
        "{%0,%1,%2,%3}, {%4,%5,%6,%7}, {%8,%9}, {%0,%1,%2,%3};"
        : "+f"(d[0]), "+f"(d[1]), "+f"(d[2]), "+f"(d[3])
        : "r"(a[0]), "r"(a[1]), "r"(a[2]), "r"(a[3]), "r"(b[0]), "r"(b[1]));
}

// streaming (evict-first) float2 STORE — for the once-written final output
__device__ __forceinline__ void stcs2(float* p, float2 v) {
    asm volatile("st.global.cs.v2.f32 [%0], {%1,%2};" :: "l"(p), "f"(v.x), "f"(v.y)
                 : "memory");
}

#define AS32_STR 20   // u32 stride per row: (20r+c) mod 32 over frag set = permutation

// =============================================================================
// BN=64 GEMM (proven round-11 version) — used for q only.
// =============================================================================
#define AS32_CNT (128 * AS32_STR)    // 2560 u32 per A buffer
#define WS32_CNT (64 * AS32_STR)     // 1280 u32 per W buffer
#define GEMM_SMEM_BYTES ((2 * AS32_CNT + 2 * WS32_CNT) * 4)    // 30720

__global__ __launch_bounds__(256) void gemm_q(
    const float* __restrict__ A, const float* __restrict__ W,
    float* __restrict__ C, int lda, int ldw, int ldc)
{
    extern __shared__ uint32_t ds[];
    uint32_t* Asb[2] = {ds, ds + AS32_CNT};
    uint32_t* Wsb[2] = {ds + 2 * AS32_CNT, ds + 2 * AS32_CNT + WS32_CNT};

    const int tid  = threadIdx.x;
    const int wid  = tid >> 5;
    const int lane = tid & 31;
    const int m0   = blockIdx.x * 128;
    const int wm   = (wid & 3) * 32;
    const int wn   = (wid >> 2) * 32;

    float4 ra[4], rw[2];
#pragma unroll
    for (int i = 0; i < 4; i++) {
        const int idx = tid + 256 * i, r = idx >> 3, kq = idx & 7;
        ra[i] = *(const float4*)(A + (size_t)(m0 + r) * lda + kq * 4);
    }
#pragma unroll
    for (int i = 0; i < 2; i++) {
        const int idx = tid + 256 * i, r = idx >> 3, kq = idx & 7;
        rw[i] = *(const float4*)(W + (size_t)r * ldw + kq * 4);
    }

    float acc[2][4][4];
#pragma unroll
    for (int i = 0; i < 2; i++)
#pragma unroll
        for (int j = 0; j < 4; j++)
#pragma unroll
            for (int v = 0; v < 4; v++) acc[i][j][v] = 0.f;

    {
        uint32_t* As = Asb[0];
        uint32_t* Ws = Wsb[0];
#pragma unroll
        for (int i = 0; i < 4; i++) {
            const int idx = tid + 256 * i, r = idx >> 3, kq = idx & 7;
            uint2 u = {packbf(ra[i].x, ra[i].y), packbf(ra[i].z, ra[i].w)};
            *(uint2*)&As[r * AS32_STR + kq * 2] = u;
        }
#pragma unroll
        for (int i = 0; i < 2; i++) {
            const int idx = tid + 256 * i, r = idx >> 3, kq = idx & 7;
            uint2 u = {packbf(rw[i].x, rw[i].y), packbf(rw[i].z, rw[i].w)};
            *(uint2*)&Ws[r * AS32_STR + kq * 2] = u;
        }
    }
    __syncthreads();

#pragma unroll 1
    for (int it = 0; it < 8; it++) {
        const int cur = it & 1;
        if (it < 7) {
            const int kb = (it + 1) * 32;
#pragma unroll
            for (int i = 0; i < 4; i++) {
                const int idx = tid + 256 * i, r = idx >> 3, kq = idx & 7;
                ra[i] = *(const float4*)(A + (size_t)(m0 + r) * lda + kb + kq * 4);
            }
#pragma unroll
            for (int i = 0; i < 2; i++) {
                const int idx = tid + 256 * i, r = idx >> 3, kq = idx & 7;
                rw[i] = *(const float4*)(W + (size_t)r * ldw + kb + kq * 4);
            }
        }
        {
            const uint32_t* As = Asb[cur];
            const uint32_t* Ws = Wsb[cur];
            const int c = lane & 3, r = lane >> 2;
#pragma unroll
            for (int ks = 0; ks < 2; ks++) {
                const int kp = ks * 8;
                uint32_t afr[2][4], bfr[4][2];
#pragma unroll
                for (int i = 0; i < 2; i++) {
                    const int r0 = wm + i * 16 + r;
                    afr[i][0] = As[r0 * AS32_STR + kp + c];
                    afr[i][1] = As[(r0 + 8) * AS32_STR + kp + c];
                    afr[i][2] = As[r0 * AS32_STR + kp + c + 4];
                    afr[i][3] = As[(r0 + 8) * AS32_STR + kp + c + 4];
                }
#pragma unroll
                for (int j = 0; j < 4; j++) {
                    const int c0 = wn + j * 8 + r;
                    bfr[j][0] = Ws[c0 * AS32_STR + kp + c];
                    bfr[j][1] = Ws[c0 * AS32_STR + kp + c + 4];
                }
#pragma unroll
                for (int i = 0; i < 2; i++)
#pragma unroll
                    for (int j = 0; j < 4; j++)
                        mma_bf16(acc[i][j], afr[i], bfr[j]);
            }
        }
        if (it < 7) {
            uint32_t* As = Asb[1 - cur];
            uint32_t* Ws = Wsb[1 - cur];
#pragma unroll
            for (int i = 0; i < 4; i++) {
                const int idx = tid + 256 * i, r = idx >> 3, kq = idx & 7;
                uint2 u = {packbf(ra[i].x, ra[i].y), packbf(ra[i].z, ra[i].w)};
                *(uint2*)&As[r * AS32_STR + kq * 2] = u;
            }
#pragma unroll
            for (int i = 0; i < 2; i++) {
                const int idx = tid + 256 * i, r = idx >> 3, kq = idx & 7;
                uint2 u = {packbf(rw[i].x, rw[i].y), packbf(rw[i].z, rw[i].w)};
                *(uint2*)&Ws[r * AS32_STR + kq * 2] = u;
            }
        }
        __syncthreads();
    }

    const int r = lane >> 2, c2 = (lane & 3) * 2;
#pragma unroll
    for (int i = 0; i < 2; i++)
#pragma unroll
        for (int j = 0; j < 4; j++) {
            const int row0 = m0 + wm + i * 16 + r;
            const int col  = wn + j * 8 + c2;
#pragma unroll
            for (int half = 0; half < 2; half++)
                *(float2*)(C + (size_t)(row0 + half * 8) * ldc + col) =
                    make_float2(acc[i][j][2 * half], acc[i][j][2 * half + 1]);
        }
}

// =============================================================================
// BN=128 GEMM body, fp32 A (gate): CTA 128x128, 8 warps 2(m)x4(n).
// NCHUNK chunks of K=32; chunk c reads A_lo if c<8 else A_hi (virtual concat).
// EPI=1: out = g*A_lo + (1-g)*A_hi, g = sigmoid(acc + bias); out via st.cs
// (written once, never re-read — evict-first keeps L2 for the GEMM's reuse).
// =============================================================================
#define W128_CNT (128 * AS32_STR)
#define GEMM128_SMEM_BYTES ((2 * AS32_CNT + 2 * W128_CNT) * 4)   // 40960

template <int NCHUNK, int EPI>
__device__ __forceinline__ void gemm_body128(
    const float* __restrict__ A_lo, const float* __restrict__ A_hi,
    const float* __restrict__ W,
    float* __restrict__ C, int lda, int ldw, int ldc, int m0, int n0,
    const float* __restrict__ bias, float* __restrict__ outp, uint32_t* ds)
{
    uint32_t* Asb[2] = {ds, ds + AS32_CNT};
    uint32_t* Wsb[2] = {ds + 2 * AS32_CNT, ds + 2 * AS32_CNT + W128_CNT};

    const int tid  = threadIdx.x;
    const int wid  = tid >> 5;
    const int lane = tid & 31;
    const int wm   = (wid & 1) * 64;
    const int wn   = (wid >> 1) * 32;

    float4 ra[4], rw[4];
#pragma unroll
    for (int i = 0; i < 4; i++) {
        const int idx = tid + 256 * i, r = idx >> 3, kq = idx & 7;
        ra[i] = *(const float4*)(A_lo + (size_t)(m0 + r) * lda + kq * 4);
        rw[i] = *(const float4*)(W + (size_t)(n0 + r) * ldw + kq * 4);
    }

    float acc[4][4][4];
#pragma unroll
    for (int i = 0; i < 4; i++)
#pragma unroll
        for (int j = 0; j < 4; j++)
#pragma unroll
            for (int v = 0; v < 4; v++) acc[i][j][v] = 0.f;

    {
        uint32_t* As = Asb[0];
        uint32_t* Ws = Wsb[0];
#pragma unroll
        for (int i = 0; i < 4; i++) {
            const int idx = tid + 256 * i, r = idx >> 3, kq = idx & 7;
            uint2 ua = {packbf(ra[i].x, ra[i].y), packbf(ra[i].z, ra[i].w)};
            uint2 uw = {packbf(rw[i].x, rw[i].y), packbf(rw[i].z, rw[i].w)};
            *(uint2*)&As[r * AS32_STR + kq * 2] = ua;
            *(uint2*)&Ws[r * AS32_STR + kq * 2] = uw;
        }
    }
    __syncthreads();

#pragma unroll 1
    for (int it = 0; it < NCHUNK; it++) {
        const int cur = it & 1;
        if (it < NCHUNK - 1) {
            const int nc = it + 1;
            const float* Abase = (NCHUNK == 8 || nc < 8) ? A_lo : A_hi;
            const int ka = (NCHUNK == 8 || nc < 8) ? nc * 32 : (nc - 8) * 32;
#pragma unroll
            for (int i = 0; i < 4; i++) {
                const int idx = tid + 256 * i, r = idx >> 3, kq = idx & 7;
                ra[i] = *(const float4*)(Abase + (size_t)(m0 + r) * lda + ka + kq * 4);
                rw[i] = *(const float4*)(W + (size_t)(n0 + r) * ldw + nc * 32 + kq * 4);
            }
        }
        {
            const uint32_t* As = Asb[cur];
            const uint32_t* Ws = Wsb[cur];
            const int c = lane & 3, r = lane >> 2;
#pragma unroll
            for (int ks = 0; ks < 2; ks++) {
                const int kp = ks * 8;
                uint32_t afr[4][4], bfr[4][2];
#pragma unroll
                for (int i = 0; i < 4; i++) {
                    const int r0 = wm + i * 16 + r;
                    afr[i][0] = As[r0 * AS32_STR + kp + c];
                    afr[i][1] = As[(r0 + 8) * AS32_STR + kp + c];
                    afr[i][2] = As[r0 * AS32_STR + kp + c + 4];
                    afr[i][3] = As[(r0 + 8) * AS32_STR + kp + c + 4];
                }
#pragma unroll
                for (int j = 0; j < 4; j++) {
                    const int c0 = wn + j * 8 + r;
                    bfr[j][0] = Ws[c0 * AS32_STR + kp + c];
                    bfr[j][1] = Ws[c0 * AS32_STR + kp + c + 4];
                }
#pragma unroll
                for (int i = 0; i < 4; i++)
#pragma unroll
                    for (int j = 0; j < 4; j++)
                        mma_bf16(acc[i][j], afr[i], bfr[j]);
            }
        }
        if (it < NCHUNK - 1) {
            uint32_t* As = Asb[1 - cur];
            uint32_t* Ws = Wsb[1 - cur];
#pragma unroll
            for (int i = 0; i < 4; i++) {
                const int idx = tid + 256 * i, r = idx >> 3, kq = idx & 7;
                uint2 ua = {packbf(ra[i].x, ra[i].y), packbf(ra[i].z, ra[i].w)};
                uint2 uw = {packbf(rw[i].x, rw[i].y), packbf(rw[i].z, rw[i].w)};
                *(uint2*)&As[r * AS32_STR + kq * 2] = ua;
                *(uint2*)&Ws[r * AS32_STR + kq * 2] = uw;
            }
        }
        __syncthreads();
    }

    const int r = lane >> 2, c2 = (lane & 3) * 2;
#pragma unroll
    for (int i = 0; i < 4; i++) {
#pragma unroll
        for (int j = 0; j < 4; j++) {
            const int row0 = m0 + wm + i * 16 + r;
            const int col  = n0 + wn + j * 8 + c2;
#pragma unroll
            for (int half = 0; half < 2; half++) {
                const int row = row0 + half * 8;
                const float d0 = acc[i][j][2 * half + 0];
                const float d1 = acc[i][j][2 * half + 1];
                if (EPI == 0) {
                    *(float2*)(C + (size_t)row * ldc + col) = make_float2(d0, d1);
                } else {
                    const float2 bv = *(const float2*)(bias + col);
                    const float2 cv = *(const float2*)(A_lo + (size_t)row * lda + col);
                    const float2 xv = *(const float2*)(A_hi + (size_t)row * lda + col);
                    const float gg0 = 1.f / (1.f + __expf(-(d0 + bv.x)));
                    const float gg1 = 1.f / (1.f + __expf(-(d1 + bv.y)));
                    float2 o;
                    o.x = gg0 * cv.x + (1.f - gg0) * xv.x;
                    o.y = gg1 * cv.y + (1.f - gg1) * xv.y;
                    stcs2(outp + (size_t)row * 256 + col, o);
                }
            }
        }
    }
}

// gate: K=512 virtual concat(center, ctx); N=256 in 2 y-blocks.
__global__ __launch_bounds__(256, 2) void gemm_gate128(
    const float* __restrict__ center, const float* __restrict__ ctx,
    const float* __restrict__ Wg, const float* __restrict__ bias,
    float* __restrict__ outp)
{
    extern __shared__ uint32_t dsu[];
    gemm_body128<16, 1>(center, ctx, Wg, nullptr, 256, 512, 0,
                        blockIdx.x * 128, blockIdx.y * 128, bias, outp, dsu);
}

// =============================================================================
// ctx GEMM, bf16 A (wn is pre-packed bf16x2): CTA 128x128, head = blockIdx.y.
// =============================================================================
__global__ __launch_bounds__(256, 2) void gemm_ctx_bf(
    const uint32_t* __restrict__ wnp, const float* __restrict__ Wv,
    float* __restrict__ ctx_)
{
    extern __shared__ uint32_t dsu[];
    uint32_t* Asb[2] = {dsu, dsu + AS32_CNT};
    uint32_t* Wsb[2] = {dsu + 2 * AS32_CNT, dsu + 2 * AS32_CNT + W128_CNT};

    const int h = blockIdx.y;
    const uint32_t* A = wnp + h * 128;         // row stride 256 u32
    const float* W = Wv + h * 128 * 256;       // [128, 256] for this head
    float* C = ctx_ + h * 128;

    const int tid  = threadIdx.x;
    const int wid  = tid >> 5;
    const int lane = tid & 31;
    const int m0   = blockIdx.x * 128;
    const int wm   = (wid & 1) * 64;
    const int wn   = (wid >> 1) * 32;

    uint2 ra[4];
    float4 rw[4];
#pragma unroll
    for (int i = 0; i < 4; i++) {
        const int idx = tid + 256 * i, r = idx >> 3, kq = idx & 7;
        ra[i] = *(const uint2*)(A + (size_t)(m0 + r) * 256 + kq * 2);
        rw[i] = *(const float4*)(W + (size_t)r * 256 + kq * 4);
    }

    float acc[4][4][4];
#pragma unroll
    for (int i = 0; i < 4; i++)
#pragma unroll
        for (int j = 0; j < 4; j++)
#pragma unroll
            for (int v = 0; v < 4; v++) acc[i][j][v] = 0.f;

    {
        uint32_t* As = Asb[0];
        uint32_t* Ws = Wsb[0];
#pragma unroll
        for (int i = 0; i < 4; i++) {
            const int idx = tid + 256 * i, r = idx >> 3, kq = idx & 7;
            *(uint2*)&As[r * AS32_STR + kq * 2] = ra[i];
            uint2 uw = {packbf(rw[i].x, rw[i].y), packbf(rw[i].z, rw[i].w)};
            *(uint2*)&Ws[r * AS32_STR + kq * 2] = uw;
        }
    }
    __syncthreads();

#pragma unroll 1
    for (int it = 0; it < 8; it++) {
        const int cur = it & 1;
        if (it < 7) {
            const int nc = it + 1;
#pragma unroll
            for (int i = 0; i < 4; i++) {
                const int idx = tid + 256 * i, r = idx >> 3, kq = idx & 7;
                ra[i] = *(const uint2*)(A + (size_t)(m0 + r) * 256 + nc * 16 + kq * 2);
                rw[i] = *(const float4*)(W + (size_t)r * 256 + nc * 32 + kq * 4);
            }
        }
        {
            const uint32_t* As = Asb[cur];
            const uint32_t* Ws = Wsb[cur];
            const int c = lane & 3, r = lane >> 2;
#pragma unroll
            for (int ks = 0; ks < 2; ks++) {
                const int kp = ks * 8;
                uint32_t afr[4][4], bfr[4][2];
#pragma unroll
                for (int i = 0; i < 4; i++) {
                    const int r0 = wm + i * 16 + r;
                    afr[i][0] = As[r0 * AS32_STR + kp + c];
                    afr[i][1] = As[(r0 + 8) * AS32_STR + kp + c];
                    afr[i][2] = As[r0 * AS32_STR + kp + c + 4];
                    afr[i][3] = As[(r0 + 8) * AS32_STR + kp + c + 4];
                }
#pragma unroll
                for (int j = 0; j < 4; j++) {
                    const int c0 = wn + j * 8 + r;
                    bfr[j][0] = Ws[c0 * AS32_STR + kp + c];
                    bfr[j][1] = Ws[c0 * AS32_STR + kp + c + 4];
                }
#pragma unroll
                for (int i = 0; i < 4; i++)
#pragma unroll
                    for (int j = 0; j < 4; j++)
                        mma_bf16(acc[i][j], afr[i], bfr[j]);
            }
        }
        if (it < 7) {
            uint32_t* As = Asb[1 - cur];
            uint32_t* Ws = Wsb[1 - cur];
#pragma unroll
            for (int i = 0; i < 4; i++) {
                const int idx = tid + 256 * i, r = idx >> 3, kq = idx & 7;
                *(uint2*)&As[r * AS32_STR + kq * 2] = ra[i];
                uint2 uw = {packbf(rw[i].x, rw[i].y), packbf(rw[i].z, rw[i].w)};
                *(uint2*)&Ws[r * AS32_STR + kq * 2] = uw;
            }
        }
        __syncthreads();
    }

    const int r = lane >> 2, c2 = (lane & 3) * 2;
#pragma unroll
    for (int i = 0; i < 4; i++)
#pragma unroll
        for (int j = 0; j < 4; j++) {
            const int row0 = m0 + wm + i * 16 + r;
            const int col  = wn + j * 8 + c2;
#pragma unroll
            for (int half = 0; half < 2; half++)
                *(float2*)(C + (size_t)(row0 + half * 8) * 256 + col) =
                    make_float2(acc[i][j][2 * half], acc[i][j][2 * half + 1]);
        }
}

// =============================================================================
// p kernel:  p[b,h,d] = sum_{a<32} q[b, h*32+a] * Wk[h*32+a, d]   (fp32)
// =============================================================================
__global__ __launch_bounds__(256) void p_kernel(const float* __restrict__ Wk)
{
    __shared__ float qs[16 * 64];
    const int t = threadIdx.x;              // t == d
    float wk[64];
#pragma unroll
    for (int r = 0; r < 64; r++) wk[r] = Wk[r * 256 + t];

    const int b0 = blockIdx.x * 16;
    const float4* qsrc = (const float4*)(g_q + (size_t)b0 * 64);
    ((float4*)qs)[t] = qsrc[t];
    __syncthreads();

#pragma unroll 1
    for (int bb = 0; bb < 16; bb++) {
        float p0 = 0.f, p1 = 0.f;
#pragma unroll
        for (int a4 = 0; a4 < 8; a4++) {
            const float4 q0 = *(const float4*)&qs[bb * 64 + a4 * 4];
            const float4 q1 = *(const float4*)&qs[bb * 64 + 32 + a4 * 4];
            p0 = fmaf(q0.x, wk[a4 * 4 + 0], p0);
            p0 = fmaf(q0.y, wk[a4 * 4 + 1], p0);
            p0 = fmaf(q0.z, wk[a4 * 4 + 2], p0);
            p0 = fmaf(q0.w, wk[a4 * 4 + 3], p0);
            p1 = fmaf(q1.x, wk[32 + a4 * 4 + 0], p1);
            p1 = fmaf(q1.y, wk[32 + a4 * 4 + 1], p1);
            p1 = fmaf(q1.z, wk[32 + a4 * 4 + 2], p1);
            p1 = fmaf(q1.w, wk[32 + a4 * 4 + 3], p1);
        }
        const size_t o = (size_t)(b0 + bb) * 512;
        g_p[o + t]       = p0;
        g_p[o + 256 + t] = p1;
    }
}

// =============================================================================
// Register-resident attention (round-14 proven version: plain LDG.128 neigh
// loads — the .cs variant measured 12us SLOWER — plus packed-bf16 wn epilogue).
// =============================================================================
__global__ __launch_bounds__(256) void attn_reg(
    const float* __restrict__ neigh, const float* __restrict__ wts)
{
    __shared__ float sAcc[8][512];        // 16 KB cross-warp reduction
    __shared__ float sScore[2][64];
    __shared__ float sAttn[2][64];
    __shared__ float sWt[64];

    const int b    = blockIdx.x;
    const int t    = threadIdx.x;
    const int w    = t >> 5;
    const int lane = t & 31;

    if (t < 64) sWt[t] = wts[(size_t)b * 64 + t] * 0.17677669529663687f; // /sqrt(32)

    const float4* pp = (const float4*)(g_p + (size_t)b * 512);
    const float4 p0a = pp[lane];
    const float4 p0b = pp[32 + lane];
    const float4 p1a = pp[64 + lane];
    const float4 p1b = pp[96 + lane];

    const float* nbp = neigh + (size_t)b * 64 * 256;

    float4 va[8], vb[8];
#pragma unroll
    for (int it = 0; it < 8; it++) {            // front-batched: 16 LDG.128
        const int k = it * 8 + w;
        va[it] = *(const float4*)(nbp + k * 256 + 4 * lane);
        vb[it] = *(const float4*)(nbp + k * 256 + 128 + 4 * lane);
    }

#pragma unroll
    for (int it = 0; it < 8; it++) {
        float s0 = va[it].x * p0a.x + va[it].y * p0a.y + va[it].z * p0a.z + va[it].w * p0a.w
                 + vb[it].x * p0b.x + vb[it].y * p0b.y + vb[it].z * p0b.z + vb[it].w * p0b.w;
        float s1 = va[it].x * p1a.x + va[it].y * p1a.y + va[it].z * p1a.z + va[it].w * p1a.w
                 + vb[it].x * p1b.x + vb[it].y * p1b.y + vb[it].z * p1b.z + vb[it].w * p1b.w;
#pragma unroll
        for (int o = 16; o; o >>= 1) {
            s0 += __shfl_xor_sync(0xffffffffu, s0, o);
            s1 += __shfl_xor_sync(0xffffffffu, s1, o);
        }
        if (lane == 0) {
            sScore[0][it * 8 + w] = s0;
            sScore[1][it * 8 + w] = s1;
        }
    }
    __syncthreads();

    if (t < 64) {                    // warps 0,1: one head each
        const int h = t >> 5, l = t & 31;
        const float sa = sScore[h][l]      * sWt[l];
        const float sb = sScore[h][32 + l] * sWt[32 + l];
        float mx = fmaxf(sa, sb);
#pragma unroll
        for (int o = 16; o; o >>= 1) mx = fmaxf(mx, __shfl_xor_sync(0xffffffffu, mx, o));
        const float ea = __expf(sa - mx), eb = __expf(sb - mx);
        float sum = ea + eb;
#pragma unroll
        for (int o = 16; o; o >>= 1) sum += __shfl_xor_sync(0xffffffffu, sum, o);
        const float inv = 1.f / sum;
        sAttn[h][l]      = ea * inv;
        sAttn[h][32 + l] = eb * inv;
    }
    __syncthreads();

    float4 a0a = {0,0,0,0}, a0b = {0,0,0,0}, a1a = {0,0,0,0}, a1b = {0,0,0,0};
#pragma unroll
    for (int it = 0; it < 8; it++) {
        const float w0 = sAttn[0][it * 8 + w];   // warp-uniform broadcast
        const float w1 = sAttn[1][it * 8 + w];
        a0a.x = fmaf(w0, va[it].x, a0a.x);  a0a.y = fmaf(w0, va[it].y, a0a.y);
        a0a.z = fmaf(w0, va[it].z, a0a.z);  a0a.w = fmaf(w0, va[it].w, a0a.w);
        a0b.x = fmaf(w0, vb[it].x, a0b.x);  a0b.y = fmaf(w0, vb[it].y, a0b.y);
        a0b.z = fmaf(w0, vb[it].z, a0b.z);  a0b.w = fmaf(w0, vb[it].w, a0b.w);
        a1a.x = fmaf(w1, va[it].x, a1a.x);  a1a.y = fmaf(w1, va[it].y, a1a.y);
        a1a.z = fmaf(w1, va[it].z, a1a.z);  a1a.w = fmaf(w1, va[it].w, a1a.w);
        a1b.x = fmaf(w1, vb[it].x, a1b.x);  a1b.y = fmaf(w1, vb[it].y, a1b.y);
        a1b.z = fmaf(w1, vb[it].z, a1b.z);  a1b.w = fmaf(w1, vb[it].w, a1b.w);
    }

    float4* row = (float4*)&sAcc[w][0];
    row[lane]      = a0a;
    row[32 + lane] = a0b;
    row[64 + lane] = a1a;
    row[96 + lane] = a1b;
    __syncthreads();

    // thread t -> one u32 of packed wn: head h = t>>7, bf16 cols 2*(t&127), +1
    const int hh = t >> 7;
    const int c0 = hh * 256 + (t & 127) * 2;
    float s_e = 0.f, s_o = 0.f;
#pragma unroll
    for (int ww = 0; ww < 8; ww++) {
        const float2 v = *(const float2*)&sAcc[ww][c0];
        s_e += v.x;
        s_o += v.y;
    }
    g_wn[(size_t)b * 256 + t] = packbf(s_e, s_o);
}

// =============================================================================
extern "C" void kernel_launch(void* const* d_in, const int* in_sizes, int n_in,
                              void* d_out, int out_size)
{
    const float* center = (const float*)d_in[0];
    const float* neigh  = (const float*)d_in[1];
    const float* wts    = (const float*)d_in[2];
    const float* Wq     = (const float*)d_in[3];
    const float* Wk     = (const float*)d_in[4];
    const float* Wv     = (const float*)d_in[5];
    const float* Wg     = (const float*)d_in[6];
    const float* bg     = (const float*)d_in[7];
    float* out = (float*)d_out;

    float *q_, *ctx_;
    uint32_t* wn_;
    cudaGetSymbolAddress((void**)&q_,   g_q);
    cudaGetSymbolAddress((void**)&wn_,  g_wn);
    cudaGetSymbolAddress((void**)&ctx_, g_ctx);

    cudaFuncSetAttribute(gemm_q,
                         cudaFuncAttributeMaxDynamicSharedMemorySize, GEMM_SMEM_BYTES);
    cudaFuncSetAttribute(gemm_ctx_bf,
                         cudaFuncAttributeMaxDynamicSharedMemorySize, GEMM128_SMEM_BYTES);
    cudaFuncSetAttribute(gemm_gate128,
                         cudaFuncAttributeMaxDynamicSharedMemorySize, GEMM128_SMEM_BYTES);

    const dim3 blk(256);

    // q = center @ Wq^T                       [B,64]
    gemm_q<<<dim3(256), blk, GEMM_SMEM_BYTES>>>(center, Wq, q_, 256, 256, 64);
    // p[b,h] = q[b,h] @ Wk_h                  [B,2,256]
    p_kernel<<<2048, blk>>>(Wk);
    // attention -> wn (packed bf16x2)         [B,512]
    attn_reg<<<NB, blk>>>(neigh, wts);
    // context_h = wn_h @ Wv_h^T               [B,256] (head = blockIdx.y)
    gemm_ctx_bf<<<dim3(256, 2), blk, GEMM128_SMEM_BYTES>>>(wn_, Wv, ctx_);
    // gate = sigmoid(concat(center,ctx) @ Wg^T + bg); out = gate*center+(1-gate)*ctx
    gemm_gate128<<<dim3(256, 2), blk, GEMM128_SMEM_BYTES>>>(center, ctx_, Wg, bg, out);
}